// round 14
// baseline (speedup 1.0000x reference)
#include <cuda_runtime.h>
#include <cuda_fp16.h>
#include <math.h>
#include <stdint.h>

#define NTOK 32768
#define SLEN 1024
#define DMOD 512
#define DFF  2048
#define NBH  256
#define HDK  64
#define BHSZ 16777216   // NBH*SLEN*HDK

typedef __half  f16;
typedef __half2 f162;

// ---- device scratch (no allocation allowed) ----
__device__ __align__(16) float g_t1[NTOK * DMOD];
__device__ __align__(16) float g_h[NTOK * DMOD];
__device__ __align__(16) f16  g_x1[NTOK * DMOD];          // x single fp16
__device__ __align__(16) f16  g_c1[NTOK * DMOD];          // ctx single fp16
__device__ __align__(16) f16  g_h1[NTOK * DMOD];          // h single fp16
__device__ __align__(16) f16  g_f1[NTOK * DFF];           // ff single fp16
__device__ __align__(16) f16  g_wh[3145728], g_wl[3145728];  // weights hi/lo fp16
__device__ __align__(16) f16  g_q1[BHSZ];                 // q single
__device__ __align__(16) f16  g_kv3[3][BHSZ];             // kh, kl, v
// weight offsets in g_wh/g_wl (elems): q=0 k=262144 v=524288 o=786432 w1=1048576 w2=2097152

// ---- helpers ----
__device__ __forceinline__ uint32_t smem_u32(const void* p) {
    uint32_t a;
    asm("{ .reg .u64 t; cvta.to.shared.u64 t, %1; cvt.u32.u64 %0, t; }" : "=r"(a) : "l"(p));
    return a;
}
__device__ __forceinline__ void split2h(float v, f16& h, float& l) {
    h = __float2half_rn(v);
    l = v - __half2float(h);
}
__device__ __forceinline__ void ldsm_x4(uint32_t* r, uint32_t a) {
    asm volatile("ldmatrix.sync.aligned.m8n8.x4.shared.b16 {%0,%1,%2,%3}, [%4];"
        : "=r"(r[0]), "=r"(r[1]), "=r"(r[2]), "=r"(r[3]) : "r"(a));
}
__device__ __forceinline__ void ldsm_x4_t(uint32_t* r, uint32_t a) {
    asm volatile("ldmatrix.sync.aligned.m8n8.x4.trans.shared.b16 {%0,%1,%2,%3}, [%4];"
        : "=r"(r[0]), "=r"(r[1]), "=r"(r[2]), "=r"(r[3]) : "r"(a));
}
__device__ __forceinline__ void ldsm_x2(uint32_t* r, uint32_t a) {
    asm volatile("ldmatrix.sync.aligned.m8n8.x2.shared.b16 {%0,%1}, [%2];"
        : "=r"(r[0]), "=r"(r[1]) : "r"(a));
}
__device__ __forceinline__ void mma_f16(float* c, const uint32_t* a, const uint32_t* b) {
    asm volatile("mma.sync.aligned.m16n8k16.row.col.f32.f16.f16.f32 "
        "{%0,%1,%2,%3}, {%4,%5,%6,%7}, {%8,%9}, {%0,%1,%2,%3};"
        : "+f"(c[0]), "+f"(c[1]), "+f"(c[2]), "+f"(c[3])
        : "r"(a[0]), "r"(a[1]), "r"(a[2]), "r"(a[3]), "r"(b[0]), "r"(b[1]));
}
__device__ __forceinline__ uint32_t pack_f16(float lo, float hi) {
    uint32_t r;
    asm("cvt.rn.f16x2.f32 %0, %1, %2;" : "=r"(r) : "f"(hi), "f"(lo));
    return r;
}
// fast exp2 on FMA pipe: floor + deg-5 poly + exponent splice (x <= 0)
__device__ __forceinline__ float fexp2(float x) {
    x = fmaxf(x, -110.0f);
    float fl = floorf(x);
    float f = x - fl;
    float p = 0.0013334f;
    p = p * f + 0.0096183f;
    p = p * f + 0.0555042f;
    p = p * f + 0.2402265f;
    p = p * f + 0.6931472f;
    p = p * f + 1.0f;
    return p * __int_as_float(((int)fl + 127) << 23);
}
#define CP_ASYNC16(dst, src) \
    asm volatile("cp.async.cg.shared.global [%0], [%1], 16;" :: "r"(dst), "l"(src))
#define CP_COMMIT() asm volatile("cp.async.commit_group;" ::: "memory")
#define CP_WAIT1()  asm volatile("cp.async.wait_group 1;" ::: "memory")
#define CP_WAIT0()  asm volatile("cp.async.wait_group 0;" ::: "memory")

// ===========================================================================
// Unified split: weights -> fp16 hi/lo; x -> single fp16. One launch.
// ===========================================================================
__global__ __launch_bounds__(256) void split_all(
    const float4* __restrict__ wq, const float4* __restrict__ wk,
    const float4* __restrict__ wv, const float4* __restrict__ wo,
    const float4* __restrict__ w1, const float4* __restrict__ w2,
    const float4* __restrict__ x,
    f162* __restrict__ wh2, f162* __restrict__ wl2,
    f162* __restrict__ xh2)
{
    const int b = blockIdx.x;
    const float4* src; f162 *hi, *lo; int i; bool single = false;
    if (b < 1024) {
        const int seg = b >> 8;
        src = (seg == 0) ? wq : (seg == 1) ? wk : (seg == 2) ? wv : wo;
        i = (b & 255) * 256 + threadIdx.x;
        hi = wh2 + (size_t)seg * 131072;
        lo = wl2 + (size_t)seg * 131072;
    } else if (b < 2048) {
        src = w1; i = (b - 1024) * 256 + threadIdx.x;
        hi = wh2 + 524288; lo = wl2 + 524288;
    } else if (b < 3072) {
        src = w2; i = (b - 2048) * 256 + threadIdx.x;
        hi = wh2 + 1048576; lo = wl2 + 1048576;
    } else {
        src = x;  i = (b - 3072) * 256 + threadIdx.x;
        hi = xh2; lo = nullptr; single = true;
    }
    float4 v = src[i];
    f16 hx, hy, hz, hw; float lx, ly, lz, lw;
    split2h(v.x, hx, lx); split2h(v.y, hy, ly);
    split2h(v.z, hz, lz); split2h(v.w, hw, lw);
    f162 a, bb;
    a.x = hx; a.y = hy; bb.x = hz; bb.y = hw;
    hi[2 * i] = a; hi[2 * i + 1] = bb;
    if (!single) {
        a.x = __float2half_rn(lx); a.y = __float2half_rn(ly);
        bb.x = __float2half_rn(lz); bb.y = __float2half_rn(lw);
        lo[2 * i] = a; lo[2 * i + 1] = bb;
    }
}

// ===========================================================================
// fp16 2-MMA GEMM (NT): C[m,n] = sum_k A[m,k]*(Wh+Wl)[n,k] + bias[n]
// A single fp16 (activations), W split hi/lo. 128x128 CTA tile, 8 warps of
// 64x32, BK=64 (144B-padded rows), 2-stage cp.async (110.6KB -> 2 CTAs/SM).
// MODE 0: fp32 store  MODE 1: GELU -> fp16  MODE 2: QKV scatter (z: q/k/v)
// ===========================================================================
#define GROWB 144
#define TILE_BYTES (128 * GROWB)        // 18432
#define STG_BYTES  (3 * TILE_BYTES)     // 55296
#define GEMM_SMEM  (2 * STG_BYTES)      // 110592

template<int MODE>
__global__ __launch_bounds__(256, 2) void tc_gemm(
    const f16* __restrict__ A, int K, int N,
    const f16* __restrict__ Wh, const f16* __restrict__ Wl,
    const float* __restrict__ b0, const float* __restrict__ b1, const float* __restrict__ b2,
    float* __restrict__ C0, f16* __restrict__ F0)
{
    const float* bias = b0; float* C = C0;
    f16 *Hd = F0, *Ld = nullptr;
    bool klmode = false;
    if (MODE == 2) {
        Wh += (size_t)blockIdx.z * 262144; Wl += (size_t)blockIdx.z * 262144;
        if (blockIdx.z == 0)      { Hd = g_q1; }
        else if (blockIdx.z == 1) { Hd = g_kv3[0]; Ld = g_kv3[1]; bias = b1; klmode = true; }
        else                      { Hd = g_kv3[2]; bias = b2; }
    }
    extern __shared__ char dynsm[];
    const uint32_t smb = smem_u32(dynsm);

    const int tid = threadIdx.x;
    const int lane = tid & 31;
    const int wr = (tid >> 5) >> 2;      // 0..1
    const int wc = (tid >> 5) & 3;       // 0..3
    const int bm = blockIdx.y << 7, bn = blockIdx.x << 7;
    const int nch = K >> 6;              // BK = 64

    const int row = tid >> 1, half = tid & 1;
    const f16* pa  = A  + (size_t)(bm + row) * K + half * 32;
    const f16* pbh = Wh + (size_t)(bn + row) * K + half * 32;
    const f16* pbl = Wl + (size_t)(bn + row) * K + half * 32;
    const uint32_t sdst = smb + row * GROWB + half * 64;

#define LOAD_CHUNK(c, s) do { \
    const uint32_t d_ = sdst + (uint32_t)(s) * STG_BYTES; \
    const size_t  g_ = (size_t)(c) * 64; \
    CP_ASYNC16(d_ + 0 * TILE_BYTES,      pa  + g_); \
    CP_ASYNC16(d_ + 0 * TILE_BYTES + 16, pa  + g_ + 8); \
    CP_ASYNC16(d_ + 0 * TILE_BYTES + 32, pa  + g_ + 16); \
    CP_ASYNC16(d_ + 0 * TILE_BYTES + 48, pa  + g_ + 24); \
    CP_ASYNC16(d_ + 1 * TILE_BYTES,      pbh + g_); \
    CP_ASYNC16(d_ + 1 * TILE_BYTES + 16, pbh + g_ + 8); \
    CP_ASYNC16(d_ + 1 * TILE_BYTES + 32, pbh + g_ + 16); \
    CP_ASYNC16(d_ + 1 * TILE_BYTES + 48, pbh + g_ + 24); \
    CP_ASYNC16(d_ + 2 * TILE_BYTES,      pbl + g_); \
    CP_ASYNC16(d_ + 2 * TILE_BYTES + 16, pbl + g_ + 8); \
    CP_ASYNC16(d_ + 2 * TILE_BYTES + 32, pbl + g_ + 16); \
    CP_ASYNC16(d_ + 2 * TILE_BYTES + 48, pbl + g_ + 24); \
} while (0)

    uint32_t arow_off[4], brow_off[4];
#pragma unroll
    for (int mi = 0; mi < 4; ++mi)
        arow_off[mi] = (uint32_t)((wr * 64 + mi * 16 + (lane & 15)) * GROWB + (lane >> 4) * 16);
#pragma unroll
    for (int ni = 0; ni < 4; ++ni)
        brow_off[ni] = (uint32_t)((wc * 32 + ni * 8 + (lane & 7)) * GROWB + ((lane >> 3) & 1) * 16);

    float acc[4][4][4];
#pragma unroll
    for (int mi = 0; mi < 4; ++mi)
#pragma unroll
        for (int ni = 0; ni < 4; ++ni)
#pragma unroll
            for (int t = 0; t < 4; ++t) acc[mi][ni][t] = 0.f;

    LOAD_CHUNK(0, 0); CP_COMMIT();

    for (int c = 0; c < nch; ++c) {
        CP_WAIT0();
        __syncthreads();
        if (c + 1 < nch) LOAD_CHUNK(c + 1, (c + 1) & 1);
        CP_COMMIT();

        const uint32_t sA = smb + (uint32_t)(c & 1) * STG_BYTES;
#pragma unroll
        for (int ks = 0; ks < 4; ++ks) {
            uint32_t ah[4][4], bh[4][2];
#pragma unroll
            for (int mi = 0; mi < 4; ++mi)
                ldsm_x4(ah[mi], sA + arow_off[mi] + ks * 32);
#pragma unroll
            for (int ni = 0; ni < 4; ++ni)
                ldsm_x2(bh[ni], sA + TILE_BYTES + brow_off[ni] + ks * 32);
#pragma unroll
            for (int mi = 0; mi < 4; ++mi)
#pragma unroll
                for (int ni = 0; ni < 4; ++ni)
                    mma_f16(acc[mi][ni], ah[mi], bh[ni]);
            uint32_t bl[4][2];
#pragma unroll
            for (int ni = 0; ni < 4; ++ni)
                ldsm_x2(bl[ni], sA + 2 * TILE_BYTES + brow_off[ni] + ks * 32);
#pragma unroll
            for (int mi = 0; mi < 4; ++mi)
#pragma unroll
                for (int ni = 0; ni < 4; ++ni)
                    mma_f16(acc[mi][ni], ah[mi], bl[ni]);
        }
    }

    // ---- epilogue ----
#pragma unroll
    for (int mi = 0; mi < 4; ++mi) {
#pragma unroll
        for (int ni = 0; ni < 4; ++ni) {
            const int col = bn + wc * 32 + ni * 8 + (lane & 3) * 2;
            const float2 bb = *(const float2*)(bias + col);
#pragma unroll
            for (int hrow = 0; hrow < 2; ++hrow) {
                const int r = bm + wr * 64 + mi * 16 + (lane >> 2) + hrow * 8;
                float v0 = acc[mi][ni][hrow * 2 + 0] + bb.x;
                float v1 = acc[mi][ni][hrow * 2 + 1] + bb.y;
                if (MODE == 1) {
                    v0 = 0.5f * v0 * (1.0f + erff(v0 * 0.70710678118654752f));
                    v1 = 0.5f * v1 * (1.0f + erff(v1 * 0.70710678118654752f));
                    f162 a;
                    a.x = __float2half_rn(v0); a.y = __float2half_rn(v1);
                    ((f162*)Hd)[((size_t)r * N + col) >> 1] = a;
                } else if (MODE == 2) {
                    const int hidx = ((r >> 10) << 3) + (col >> 6);
                    const size_t idx = (size_t)hidx * (SLEN * HDK)
                                     + ((r & 1023) << 6) + (col & 63);
                    if (klmode) {
                        f16 h0, h1; float l0, l1;
                        split2h(v0, h0, l0); split2h(v1, h1, l1);
                        f162 a; a.x = h0; a.y = h1;
                        ((f162*)Hd)[idx >> 1] = a;
                        a.x = __float2half_rn(l0); a.y = __float2half_rn(l1);
                        ((f162*)Ld)[idx >> 1] = a;
                    } else {
                        f162 a;
                        a.x = __float2half_rn(v0); a.y = __float2half_rn(v1);
                        ((f162*)Hd)[idx >> 1] = a;
                    }
                } else {
                    *(float2*)(C + (size_t)r * N + col) = make_float2(v0, v1);
                }
            }
        }
    }
}

// ===========================================================================
// Tensor-core flash attention, fp16. 2 CTAs/SM.
// grid=(8, 256), block=256 (8 warps, 16 query rows each).
// QK = qh·(kh+kl) (2 MMAs), PV = fp16 P x fp16 V (1 MMA).
// ===========================================================================
#define ROWB 144
#define KVTILE (64 * ROWB)        // 9216
#define STAGEB (3 * KVTILE)       // 27648
#define ATTN_SMEM (2 * STAGEB)    // 55296

__global__ __launch_bounds__(256, 2) void attn_mma(const unsigned int* __restrict__ mask)
{
    extern __shared__ char sm[];
    __shared__ float s_fac[2][64];
    const uint32_t smb = smem_u32(sm);
    const int tid = threadIdx.x, wid = tid >> 5, lane = tid & 31;
    const int bh = blockIdx.y;
    const int bfi = bh >> 3, bb = bfi >> 3;
    const int q0 = blockIdx.x << 7;
    const float FB = 0.25f  * 1.4426950408889634f;
    const float FN = 0.125f * 1.4426950408889634f;

    // ---- stage Q (single fp16) through smem into A-fragments ----
#pragma unroll
    for (int i = 0; i < 4; ++i) {
        const int cid = tid + (i << 8);                  // 0..1023
        const int row = cid >> 3, c = cid & 7;
        const f16* src = g_q1 + ((size_t)bh << 16) + (size_t)(q0 + row) * 64 + c * 8;
        CP_ASYNC16(smb + row * ROWB + c * 16, src);
    }
    CP_COMMIT();
    CP_WAIT0();
    __syncthreads();

    uint32_t qh[4][4];
#pragma unroll
    for (int ks = 0; ks < 4; ++ks) {
        const uint32_t off = (wid * 16 + (lane & 15)) * ROWB + ks * 32 + (lane >> 4) * 16;
        ldsm_x4(qh[ks], smb + off);
    }
    __syncthreads();

    float o[8][4];
#pragma unroll
    for (int nt = 0; nt < 8; ++nt)
#pragma unroll
        for (int t = 0; t < 4; ++t) o[nt][t] = 0.f;
    float m0 = -1e30f, m1 = -1e30f, l0 = 0.f, l1 = 0.f;

#define LOAD_KV(kt_, st_) do { \
    _Pragma("unroll") \
    for (int i = 0; i < 6; ++i) { \
        const int cid = tid + (i << 8); \
        const int arr = cid >> 9, rem = cid & 511; \
        const int row = rem >> 3, cc = rem & 7; \
        const f16* src = g_kv3[arr] + ((size_t)bh << 16) \
                       + (size_t)(((kt_) << 6) + row) * 64 + cc * 8; \
        CP_ASYNC16(smb + (st_) * STAGEB + arr * KVTILE + row * ROWB + cc * 16, src); \
    } \
} while (0)

    LOAD_KV(0, 0);
    CP_COMMIT();
    if (tid < 64) s_fac[0][tid] = mask[bb * SLEN + tid] ? FB : FN;

    for (int kt = 0; kt < 16; ++kt) {
        const int sb = kt & 1;
        if (kt < 15) {
            LOAD_KV(kt + 1, sb ^ 1);
            CP_COMMIT();
            if (tid < 64)
                s_fac[sb ^ 1][tid] = mask[bb * SLEN + (kt + 1) * 64 + tid] ? FB : FN;
            CP_WAIT1();
        } else {
            CP_WAIT0();
        }
        __syncthreads();
        const uint32_t st = smb + sb * STAGEB;

        // ---- QK: s = qh·kh + qh·kl ----
        float s[8][4];
#pragma unroll
        for (int nt = 0; nt < 8; ++nt)
#pragma unroll
            for (int t = 0; t < 4; ++t) s[nt][t] = 0.f;
#pragma unroll
        for (int ks = 0; ks < 4; ++ks) {
#pragma unroll
            for (int gp = 0; gp < 4; ++gp) {
                uint32_t kb[4], klb[4];
                const uint32_t off = (gp * 16 + ((lane >> 4) << 3) + (lane & 7)) * ROWB
                                   + ks * 32 + ((lane >> 3) & 1) * 16;
                ldsm_x4(kb,  st + off);
                ldsm_x4(klb, st + KVTILE + off);
                mma_f16(s[2 * gp],     qh[ks], kb);
                mma_f16(s[2 * gp],     qh[ks], klb);
                mma_f16(s[2 * gp + 1], qh[ks], kb + 2);
                mma_f16(s[2 * gp + 1], qh[ks], klb + 2);
            }
        }

        // ---- softmax (log2 domain) ----
        const float* fac = s_fac[sb];
        float tm0 = -1e30f, tm1 = -1e30f;
#pragma unroll
        for (int nt = 0; nt < 8; ++nt) {
            const int c0 = nt * 8 + (lane & 3) * 2;
            const float f0 = fac[c0], f1 = fac[c0 + 1];
            s[nt][0] *= f0; s[nt][1] *= f1;
            s[nt][2] *= f0; s[nt][3] *= f1;
            tm0 = fmaxf(tm0, fmaxf(s[nt][0], s[nt][1]));
            tm1 = fmaxf(tm1, fmaxf(s[nt][2], s[nt][3]));
        }
        tm0 = fmaxf(tm0, __shfl_xor_sync(0xffffffffu, tm0, 1));
        tm0 = fmaxf(tm0, __shfl_xor_sync(0xffffffffu, tm0, 2));
        tm1 = fmaxf(tm1, __shfl_xor_sync(0xffffffffu, tm1, 1));
        tm1 = fmaxf(tm1, __shfl_xor_sync(0xffffffffu, tm1, 2));
        const float mn0 = fmaxf(m0, tm0), mn1 = fmaxf(m1, tm1);
        const float a0 = fexp2(m0 - mn0), a1 = fexp2(m1 - mn1);
        m0 = mn0; m1 = mn1;
        l0 *= a0; l1 *= a1;
#pragma unroll
        for (int nt = 0; nt < 8; ++nt) {
            o[nt][0] *= a0; o[nt][1] *= a0;
            o[nt][2] *= a1; o[nt][3] *= a1;
        }

        uint32_t pA[4][4];
        float sl0 = 0.f, sl1 = 0.f;
#pragma unroll
        for (int nt = 0; nt < 8; ++nt) {
            const float p0 = fexp2(s[nt][0] - m0), p1 = fexp2(s[nt][1] - m0);
            const float p2 = fexp2(s[nt][2] - m1), p3 = fexp2(s[nt][3] - m1);
            sl0 += p0 + p1; sl1 += p2 + p3;
            pA[nt >> 1][(nt & 1) * 2 + 0] = pack_f16(p0, p1);
            pA[nt >> 1][(nt & 1) * 2 + 1] = pack_f16(p2, p3);
        }
        sl0 += __shfl_xor_sync(0xffffffffu, sl0, 1);
        sl0 += __shfl_xor_sync(0xffffffffu, sl0, 2);
        sl1 += __shfl_xor_sync(0xffffffffu, sl1, 1);
        sl1 += __shfl_xor_sync(0xffffffffu, sl1, 2);
        l0 += sl0; l1 += sl1;

        // ---- PV: o += P · V (single fp16 V) ----
#pragma unroll
        for (int ks = 0; ks < 4; ++ks) {
#pragma unroll
            for (int np = 0; np < 4; ++np) {
                uint32_t vb[4];
                const uint32_t off = (ks * 16 + ((lane >> 3) & 1) * 8 + (lane & 7)) * ROWB
                                   + np * 32 + (lane >> 4) * 16;
                ldsm_x4_t(vb, st + 2 * KVTILE + off);
                mma_f16(o[2 * np],     pA[ks], vb);
                mma_f16(o[2 * np + 1], pA[ks], vb + 2);
            }
        }
        __syncthreads();
    }

    // ---- epilogue: o/l -> ctx single fp16 [t][h*64+dk] ----
    const float inv0 = 1.f / l0, inv1 = 1.f / l1;
    const int trow0 = bfi * SLEN + q0 + wid * 16 + (lane >> 2);
    const int colb = (bh & 7) * 64 + (lane & 3) * 2;
#pragma unroll
    for (int nt = 0; nt < 8; ++nt) {
        const int col = colb + nt * 8;
        const size_t i0 = ((size_t)trow0 * DMOD + col) >> 1;
        const size_t i1 = i0 + (8 * DMOD / 2);
        f162 a;
        a.x = __float2half_rn(o[nt][0] * inv0);
        a.y = __float2half_rn(o[nt][1] * inv0);
        ((f162*)g_c1)[i0] = a;
        a.x = __float2half_rn(o[nt][2] * inv1);
        a.y = __float2half_rn(o[nt][3] * inv1);
        ((f162*)g_c1)[i1] = a;
    }
}

// ===========================================================================
// Residual + LayerNorm; SPLIT=1 also emits single fp16 of the output.
// ===========================================================================
template<int SPLIT>
__global__ __launch_bounds__(256) void ln_kernel(
    const float* __restrict__ X, const float* __restrict__ Y,
    const float* __restrict__ gam, const float* __restrict__ bet,
    float* __restrict__ out, f162* __restrict__ oh)
{
    const int lane = threadIdx.x & 31;
    const int t = (blockIdx.x << 3) + (threadIdx.x >> 5);
    const float4* xp = (const float4*)(X + (size_t)t * DMOD);
    const float4* yp = (const float4*)(Y + (size_t)t * DMOD);

    float4 r[4];
    float sum = 0.f, sq = 0.f;
#pragma unroll
    for (int i = 0; i < 4; ++i) {
        const int idx = lane + (i << 5);
        float4 a = xp[idx], b = yp[idx];
        float4 v = make_float4(a.x + b.x, a.y + b.y, a.z + b.z, a.w + b.w);
        r[i] = v;
        sum += (v.x + v.y) + (v.z + v.w);
        sq  += (v.x * v.x + v.y * v.y) + (v.z * v.z + v.w * v.w);
    }
#pragma unroll
    for (int off = 16; off; off >>= 1) {
        sum += __shfl_xor_sync(0xffffffffu, sum, off);
        sq  += __shfl_xor_sync(0xffffffffu, sq, off);
    }
    const float mean = sum * (1.0f / 512.0f);
    const float var  = sq * (1.0f / 512.0f) - mean * mean;
    const float rstd = rsqrtf(var + 1e-5f);

    float4* op = (float4*)(out + (size_t)t * DMOD);
    const float4* gp = (const float4*)gam;
    const float4* bp = (const float4*)bet;
#pragma unroll
    for (int i = 0; i < 4; ++i) {
        const int idx = lane + (i << 5);
        float4 g = gp[idx], be = bp[idx], v = r[i];
        float4 o4;
        o4.x = (v.x - mean) * rstd * g.x + be.x;
        o4.y = (v.y - mean) * rstd * g.y + be.y;
        o4.z = (v.z - mean) * rstd * g.z + be.z;
        o4.w = (v.w - mean) * rstd * g.w + be.w;
        op[idx] = o4;
        if (SPLIT) {
            f162 a, b2;
            a.x = __float2half_rn(o4.x); a.y = __float2half_rn(o4.y);
            b2.x = __float2half_rn(o4.z); b2.y = __float2half_rn(o4.w);
            oh[(size_t)t * 256 + idx * 2]     = a;
            oh[(size_t)t * 256 + idx * 2 + 1] = b2;
        }
    }
}

// ===========================================================================
extern "C" void kernel_launch(void* const* d_in, const int* in_sizes, int n_in,
                              void* d_out, int out_size)
{
    const float* x   = (const float*)d_in[0];
    const unsigned int* mask = (const unsigned int*)d_in[1];
    const float* wq  = (const float*)d_in[2];
    const float* bq  = (const float*)d_in[3];
    const float* wk  = (const float*)d_in[4];
    const float* bk  = (const float*)d_in[5];
    const float* wv  = (const float*)d_in[6];
    const float* bv  = (const float*)d_in[7];
    const float* wo  = (const float*)d_in[8];
    const float* bo  = (const float*)d_in[9];
    const float* w1  = (const float*)d_in[10];
    const float* b1  = (const float*)d_in[11];
    const float* w2  = (const float*)d_in[12];
    const float* b2  = (const float*)d_in[13];
    const float* g1  = (const float*)d_in[14];
    const float* be1 = (const float*)d_in[15];
    const float* g2  = (const float*)d_in[16];
    const float* be2 = (const float*)d_in[17];
    float* out = (float*)d_out;

    float *t1_p, *h_p;
    f16 *x1, *c1, *h1, *f1, *wh, *wl;
    cudaGetSymbolAddress((void**)&t1_p, g_t1);
    cudaGetSymbolAddress((void**)&h_p, g_h);
    cudaGetSymbolAddress((void**)&x1, g_x1);
    cudaGetSymbolAddress((void**)&c1, g_c1);
    cudaGetSymbolAddress((void**)&h1, g_h1);
    cudaGetSymbolAddress((void**)&f1, g_f1);
    cudaGetSymbolAddress((void**)&wh, g_wh);
    cudaGetSymbolAddress((void**)&wl, g_wl);

    cudaFuncSetAttribute(tc_gemm<0>, cudaFuncAttributeMaxDynamicSharedMemorySize, GEMM_SMEM);
    cudaFuncSetAttribute(tc_gemm<1>, cudaFuncAttributeMaxDynamicSharedMemorySize, GEMM_SMEM);
    cudaFuncSetAttribute(tc_gemm<2>, cudaFuncAttributeMaxDynamicSharedMemorySize, GEMM_SMEM);
    cudaFuncSetAttribute(attn_mma,   cudaFuncAttributeMaxDynamicSharedMemorySize, ATTN_SMEM);

    // 0) all splits (weights hi/lo + x single) in ONE launch
    split_all<<<19456, 256>>>((const float4*)wq, (const float4*)wk,
        (const float4*)wv, (const float4*)wo, (const float4*)w1, (const float4*)w2,
        (const float4*)x, (f162*)wh, (f162*)wl, (f162*)x1);

    // 1) QKV (z = 0/1/2) -> q single / k hi-lo / v single in [bh][s][dk]
    tc_gemm<2><<<dim3(4, 256, 3), 256, GEMM_SMEM>>>(x1, 512, 512,
        wh, wl, bq, bk, bv, nullptr, nullptr);

    // 2) tensor-core attention -> ctx single fp16
    attn_mma<<<dim3(8, 256), 256, ATTN_SMEM>>>(mask);

    // 3) O-proj -> t1 (fp32)
    tc_gemm<0><<<dim3(4, 256, 1), 256, GEMM_SMEM>>>(c1, 512, 512,
        wh + 786432, wl + 786432, bo, nullptr, nullptr, t1_p, nullptr);

    // 4) h = LN(x + attn_out); also single fp16 of h
    ln_kernel<1><<<NTOK / 8, 256>>>(x, t1_p, g1, be1, h_p, (f162*)h1);

    // 5) FFN up + GELU -> ff single fp16
    tc_gemm<1><<<dim3(16, 256, 1), 256, GEMM_SMEM>>>(h1, 512, 2048,
        wh + 1048576, wl + 1048576, b1, nullptr, nullptr, nullptr, f1);

    // 6) FFN down -> t1 (fp32)
    tc_gemm<0><<<dim3(4, 256, 1), 256, GEMM_SMEM>>>(f1, 2048, 512,
        wh + 2097152, wl + 2097152, b2, nullptr, nullptr, t1_p, nullptr);

    // 7) out = LN(h + ffn_out)
    ln_kernel<0><<<NTOK / 8, 256>>>(h_p, t1_p, g2, be2, out, nullptr);
}

// round 15
// speedup vs baseline: 1.0978x; 1.0978x over previous
#include <cuda_runtime.h>
#include <cuda_fp16.h>
#include <math.h>
#include <stdint.h>

#define NTOK 32768
#define SLEN 1024
#define DMOD 512
#define DFF  2048
#define NBH  256
#define HDK  64
#define BHSZ 16777216   // NBH*SLEN*HDK

typedef __half  f16;
typedef __half2 f162;

// ---- device scratch (no allocation allowed) ----
__device__ __align__(16) float g_t1[NTOK * DMOD];
__device__ __align__(16) float g_h[NTOK * DMOD];
__device__ __align__(16) f16  g_x1[NTOK * DMOD];          // x single fp16
__device__ __align__(16) f16  g_c1[NTOK * DMOD];          // ctx single fp16
__device__ __align__(16) f16  g_h1[NTOK * DMOD];          // h single fp16
__device__ __align__(16) f16  g_f1[NTOK * DFF];           // ff single fp16
__device__ __align__(16) f16  g_wh[3145728], g_wl[3145728];  // weights hi/lo fp16
__device__ __align__(16) f16  g_q1[BHSZ];                 // q single
__device__ __align__(16) f16  g_kv3[3][BHSZ];             // kh, kl, v
// weight offsets in g_wh/g_wl (elems): q=0 k=262144 v=524288 o=786432 w1=1048576 w2=2097152

// ---- helpers ----
__device__ __forceinline__ uint32_t smem_u32(const void* p) {
    uint32_t a;
    asm("{ .reg .u64 t; cvta.to.shared.u64 t, %1; cvt.u32.u64 %0, t; }" : "=r"(a) : "l"(p));
    return a;
}
__device__ __forceinline__ void split2h(float v, f16& h, float& l) {
    h = __float2half_rn(v);
    l = v - __half2float(h);
}
__device__ __forceinline__ void ldsm_x4(uint32_t* r, uint32_t a) {
    asm volatile("ldmatrix.sync.aligned.m8n8.x4.shared.b16 {%0,%1,%2,%3}, [%4];"
        : "=r"(r[0]), "=r"(r[1]), "=r"(r[2]), "=r"(r[3]) : "r"(a));
}
__device__ __forceinline__ void ldsm_x4_t(uint32_t* r, uint32_t a) {
    asm volatile("ldmatrix.sync.aligned.m8n8.x4.trans.shared.b16 {%0,%1,%2,%3}, [%4];"
        : "=r"(r[0]), "=r"(r[1]), "=r"(r[2]), "=r"(r[3]) : "r"(a));
}
__device__ __forceinline__ void ldsm_x2(uint32_t* r, uint32_t a) {
    asm volatile("ldmatrix.sync.aligned.m8n8.x2.shared.b16 {%0,%1}, [%2];"
        : "=r"(r[0]), "=r"(r[1]) : "r"(a));
}
__device__ __forceinline__ void mma_f16(float* c, const uint32_t* a, const uint32_t* b) {
    asm volatile("mma.sync.aligned.m16n8k16.row.col.f32.f16.f16.f32 "
        "{%0,%1,%2,%3}, {%4,%5,%6,%7}, {%8,%9}, {%0,%1,%2,%3};"
        : "+f"(c[0]), "+f"(c[1]), "+f"(c[2]), "+f"(c[3])
        : "r"(a[0]), "r"(a[1]), "r"(a[2]), "r"(a[3]), "r"(b[0]), "r"(b[1]));
}
__device__ __forceinline__ uint32_t pack_f16(float lo, float hi) {
    uint32_t r;
    asm("cvt.rn.f16x2.f32 %0, %1, %2;" : "=r"(r) : "f"(hi), "f"(lo));
    return r;
}
// fast exp2 on FMA pipe: floor + deg-5 poly + exponent splice (x <= 0)
__device__ __forceinline__ float fexp2(float x) {
    x = fmaxf(x, -110.0f);
    float fl = floorf(x);
    float f = x - fl;
    float p = 0.0013334f;
    p = p * f + 0.0096183f;
    p = p * f + 0.0555042f;
    p = p * f + 0.2402265f;
    p = p * f + 0.6931472f;
    p = p * f + 1.0f;
    return p * __int_as_float(((int)fl + 127) << 23);
}
#define CP_ASYNC16(dst, src) \
    asm volatile("cp.async.cg.shared.global [%0], [%1], 16;" :: "r"(dst), "l"(src))
#define CP_COMMIT() asm volatile("cp.async.commit_group;" ::: "memory")
#define CP_WAIT1()  asm volatile("cp.async.wait_group 1;" ::: "memory")
#define CP_WAIT0()  asm volatile("cp.async.wait_group 0;" ::: "memory")

// ===========================================================================
// Unified split: weights -> fp16 hi/lo; x -> single fp16. One launch.
// ===========================================================================
__global__ __launch_bounds__(256) void split_all(
    const float4* __restrict__ wq, const float4* __restrict__ wk,
    const float4* __restrict__ wv, const float4* __restrict__ wo,
    const float4* __restrict__ w1, const float4* __restrict__ w2,
    const float4* __restrict__ x,
    f162* __restrict__ wh2, f162* __restrict__ wl2,
    f162* __restrict__ xh2)
{
    const int b = blockIdx.x;
    const float4* src; f162 *hi, *lo; int i; bool single = false;
    if (b < 1024) {
        const int seg = b >> 8;
        src = (seg == 0) ? wq : (seg == 1) ? wk : (seg == 2) ? wv : wo;
        i = (b & 255) * 256 + threadIdx.x;
        hi = wh2 + (size_t)seg * 131072;
        lo = wl2 + (size_t)seg * 131072;
    } else if (b < 2048) {
        src = w1; i = (b - 1024) * 256 + threadIdx.x;
        hi = wh2 + 524288; lo = wl2 + 524288;
    } else if (b < 3072) {
        src = w2; i = (b - 2048) * 256 + threadIdx.x;
        hi = wh2 + 1048576; lo = wl2 + 1048576;
    } else {
        src = x;  i = (b - 3072) * 256 + threadIdx.x;
        hi = xh2; lo = nullptr; single = true;
    }
    float4 v = src[i];
    f16 hx, hy, hz, hw; float lx, ly, lz, lw;
    split2h(v.x, hx, lx); split2h(v.y, hy, ly);
    split2h(v.z, hz, lz); split2h(v.w, hw, lw);
    f162 a, bb;
    a.x = hx; a.y = hy; bb.x = hz; bb.y = hw;
    hi[2 * i] = a; hi[2 * i + 1] = bb;
    if (!single) {
        a.x = __float2half_rn(lx); a.y = __float2half_rn(ly);
        bb.x = __float2half_rn(lz); bb.y = __float2half_rn(lw);
        lo[2 * i] = a; lo[2 * i + 1] = bb;
    }
}

// ===========================================================================
// fp16 2-MMA GEMM (NT): C[m,n] = sum_k A[m,k]*(Wh+Wl)[n,k] + bias[n]
// A single fp16 (activations), W split hi/lo. 128x128 CTA tile, 8 warps of
// 64x32, BK=32, 2-stage cp.async (3 tiles/stage = 43KB -> 2 CTAs/SM).
// All 12 LDSM issued up front per k-half, then 32 MMAs.
// MODE 0: fp32 store  MODE 1: GELU -> fp16  MODE 2: QKV scatter (z: q/k/v)
// ===========================================================================
#define PADC 56
#define TILE_BYTES (128 * PADC * 2)     // 14336
#define STG_BYTES  (3 * TILE_BYTES)     // 43008
#define GEMM_SMEM  (2 * STG_BYTES)      // 86016

template<int MODE>
__global__ __launch_bounds__(256, 2) void tc_gemm(
    const f16* __restrict__ A, int K, int N,
    const f16* __restrict__ Wh, const f16* __restrict__ Wl,
    const float* __restrict__ b0, const float* __restrict__ b1, const float* __restrict__ b2,
    float* __restrict__ C0, f16* __restrict__ F0)
{
    const float* bias = b0; float* C = C0;
    f16 *Hd = F0, *Ld = nullptr;
    bool klmode = false;
    if (MODE == 2) {
        Wh += (size_t)blockIdx.z * 262144; Wl += (size_t)blockIdx.z * 262144;
        if (blockIdx.z == 0)      { Hd = g_q1; }
        else if (blockIdx.z == 1) { Hd = g_kv3[0]; Ld = g_kv3[1]; bias = b1; klmode = true; }
        else                      { Hd = g_kv3[2]; bias = b2; }
    }
    extern __shared__ char dynsm[];
    const uint32_t smb = smem_u32(dynsm);

    const int tid = threadIdx.x;
    const int lane = tid & 31;
    const int wr = (tid >> 5) >> 2;      // 0..1
    const int wc = (tid >> 5) & 3;       // 0..3
    const int bm = blockIdx.y << 7, bn = blockIdx.x << 7;
    const int nch = K >> 5;

    const int row = tid >> 1, half = tid & 1;
    const f16* pa  = A  + (size_t)(bm + row) * K + half * 16;
    const f16* pbh = Wh + (size_t)(bn + row) * K + half * 16;
    const f16* pbl = Wl + (size_t)(bn + row) * K + half * 16;
    const uint32_t sdst = smb + row * 112 + half * 32;

#define LOAD_CHUNK(c, s) do { \
    const uint32_t d_ = sdst + (uint32_t)(s) * STG_BYTES; \
    const size_t  g_ = (size_t)(c) * 32; \
    CP_ASYNC16(d_ + 0 * TILE_BYTES,      pa  + g_); \
    CP_ASYNC16(d_ + 0 * TILE_BYTES + 16, pa  + g_ + 8); \
    CP_ASYNC16(d_ + 1 * TILE_BYTES,      pbh + g_); \
    CP_ASYNC16(d_ + 1 * TILE_BYTES + 16, pbh + g_ + 8); \
    CP_ASYNC16(d_ + 2 * TILE_BYTES,      pbl + g_); \
    CP_ASYNC16(d_ + 2 * TILE_BYTES + 16, pbl + g_ + 8); \
} while (0)

    uint32_t arow_off[4], brow_off[4];
#pragma unroll
    for (int mi = 0; mi < 4; ++mi)
        arow_off[mi] = (uint32_t)((wr * 64 + mi * 16 + (lane & 15)) * 112 + (lane >> 4) * 16);
#pragma unroll
    for (int ni = 0; ni < 4; ++ni)
        brow_off[ni] = (uint32_t)((wc * 32 + ni * 8 + (lane & 7)) * 112 + ((lane >> 3) & 1) * 16);

    float acc[4][4][4];
#pragma unroll
    for (int mi = 0; mi < 4; ++mi)
#pragma unroll
        for (int ni = 0; ni < 4; ++ni)
#pragma unroll
            for (int t = 0; t < 4; ++t) acc[mi][ni][t] = 0.f;

    LOAD_CHUNK(0, 0); CP_COMMIT();

    for (int c = 0; c < nch; ++c) {
        CP_WAIT0();
        __syncthreads();
        if (c + 1 < nch) LOAD_CHUNK(c + 1, (c + 1) & 1);
        CP_COMMIT();

        const uint32_t sA = smb + (uint32_t)(c & 1) * STG_BYTES;
#pragma unroll
        for (int ks = 0; ks < 2; ++ks) {
            uint32_t ah[4][4], bh[4][2], bl[4][2];
#pragma unroll
            for (int mi = 0; mi < 4; ++mi)
                ldsm_x4(ah[mi], sA + arow_off[mi] + ks * 32);
#pragma unroll
            for (int ni = 0; ni < 4; ++ni) {
                ldsm_x2(bh[ni], sA + TILE_BYTES + brow_off[ni] + ks * 32);
                ldsm_x2(bl[ni], sA + 2 * TILE_BYTES + brow_off[ni] + ks * 32);
            }
#pragma unroll
            for (int mi = 0; mi < 4; ++mi)
#pragma unroll
                for (int ni = 0; ni < 4; ++ni)
                    mma_f16(acc[mi][ni], ah[mi], bh[ni]);
#pragma unroll
            for (int mi = 0; mi < 4; ++mi)
#pragma unroll
                for (int ni = 0; ni < 4; ++ni)
                    mma_f16(acc[mi][ni], ah[mi], bl[ni]);
        }
    }

    // ---- epilogue ----
#pragma unroll
    for (int mi = 0; mi < 4; ++mi) {
#pragma unroll
        for (int ni = 0; ni < 4; ++ni) {
            const int col = bn + wc * 32 + ni * 8 + (lane & 3) * 2;
            const float2 bb = *(const float2*)(bias + col);
#pragma unroll
            for (int hrow = 0; hrow < 2; ++hrow) {
                const int r = bm + wr * 64 + mi * 16 + (lane >> 2) + hrow * 8;
                float v0 = acc[mi][ni][hrow * 2 + 0] + bb.x;
                float v1 = acc[mi][ni][hrow * 2 + 1] + bb.y;
                if (MODE == 1) {
                    v0 = 0.5f * v0 * (1.0f + erff(v0 * 0.70710678118654752f));
                    v1 = 0.5f * v1 * (1.0f + erff(v1 * 0.70710678118654752f));
                    f162 a;
                    a.x = __float2half_rn(v0); a.y = __float2half_rn(v1);
                    ((f162*)Hd)[((size_t)r * N + col) >> 1] = a;
                } else if (MODE == 2) {
                    const int hidx = ((r >> 10) << 3) + (col >> 6);
                    const size_t idx = (size_t)hidx * (SLEN * HDK)
                                     + ((r & 1023) << 6) + (col & 63);
                    if (klmode) {
                        f16 h0, h1; float l0, l1;
                        split2h(v0, h0, l0); split2h(v1, h1, l1);
                        f162 a; a.x = h0; a.y = h1;
                        ((f162*)Hd)[idx >> 1] = a;
                        a.x = __float2half_rn(l0); a.y = __float2half_rn(l1);
                        ((f162*)Ld)[idx >> 1] = a;
                    } else {
                        f162 a;
                        a.x = __float2half_rn(v0); a.y = __float2half_rn(v1);
                        ((f162*)Hd)[idx >> 1] = a;
                    }
                } else {
                    *(float2*)(C + (size_t)r * N + col) = make_float2(v0, v1);
                }
            }
        }
    }
}

// ===========================================================================
// Tensor-core flash attention, fp16. 2 CTAs/SM.
// grid=(8, 256), block=256 (8 warps, 16 query rows each).
// QK = qh·(kh+kl) (2 MMAs), PV = fp16 P x fp16 V (1 MMA).
// ===========================================================================
#define ROWB 144
#define KVTILE (64 * ROWB)        // 9216
#define STAGEB (3 * KVTILE)       // 27648
#define ATTN_SMEM (2 * STAGEB)    // 55296

__global__ __launch_bounds__(256, 2) void attn_mma(const unsigned int* __restrict__ mask)
{
    extern __shared__ char sm[];
    __shared__ float s_fac[2][64];
    const uint32_t smb = smem_u32(sm);
    const int tid = threadIdx.x, wid = tid >> 5, lane = tid & 31;
    const int bh = blockIdx.y;
    const int bfi = bh >> 3, bb = bfi >> 3;
    const int q0 = blockIdx.x << 7;
    const float FB = 0.25f  * 1.4426950408889634f;
    const float FN = 0.125f * 1.4426950408889634f;

    // ---- stage Q (single fp16) through smem into A-fragments ----
#pragma unroll
    for (int i = 0; i < 4; ++i) {
        const int cid = tid + (i << 8);                  // 0..1023
        const int row = cid >> 3, c = cid & 7;
        const f16* src = g_q1 + ((size_t)bh << 16) + (size_t)(q0 + row) * 64 + c * 8;
        CP_ASYNC16(smb + row * ROWB + c * 16, src);
    }
    CP_COMMIT();
    CP_WAIT0();
    __syncthreads();

    uint32_t qh[4][4];
#pragma unroll
    for (int ks = 0; ks < 4; ++ks) {
        const uint32_t off = (wid * 16 + (lane & 15)) * ROWB + ks * 32 + (lane >> 4) * 16;
        ldsm_x4(qh[ks], smb + off);
    }
    __syncthreads();

    float o[8][4];
#pragma unroll
    for (int nt = 0; nt < 8; ++nt)
#pragma unroll
        for (int t = 0; t < 4; ++t) o[nt][t] = 0.f;
    float m0 = -1e30f, m1 = -1e30f, l0 = 0.f, l1 = 0.f;

#define LOAD_KV(kt_, st_) do { \
    _Pragma("unroll") \
    for (int i = 0; i < 6; ++i) { \
        const int cid = tid + (i << 8); \
        const int arr = cid >> 9, rem = cid & 511; \
        const int row = rem >> 3, cc = rem & 7; \
        const f16* src = g_kv3[arr] + ((size_t)bh << 16) \
                       + (size_t)(((kt_) << 6) + row) * 64 + cc * 8; \
        CP_ASYNC16(smb + (st_) * STAGEB + arr * KVTILE + row * ROWB + cc * 16, src); \
    } \
} while (0)

    LOAD_KV(0, 0);
    CP_COMMIT();
    if (tid < 64) s_fac[0][tid] = mask[bb * SLEN + tid] ? FB : FN;

    for (int kt = 0; kt < 16; ++kt) {
        const int sb = kt & 1;
        if (kt < 15) {
            LOAD_KV(kt + 1, sb ^ 1);
            CP_COMMIT();
            if (tid < 64)
                s_fac[sb ^ 1][tid] = mask[bb * SLEN + (kt + 1) * 64 + tid] ? FB : FN;
            CP_WAIT1();
        } else {
            CP_WAIT0();
        }
        __syncthreads();
        const uint32_t st = smb + sb * STAGEB;

        // ---- QK: s = qh·kh + qh·kl ----
        float s[8][4];
#pragma unroll
        for (int nt = 0; nt < 8; ++nt)
#pragma unroll
            for (int t = 0; t < 4; ++t) s[nt][t] = 0.f;
#pragma unroll
        for (int ks = 0; ks < 4; ++ks) {
#pragma unroll
            for (int gp = 0; gp < 4; ++gp) {
                uint32_t kb[4], klb[4];
                const uint32_t off = (gp * 16 + ((lane >> 4) << 3) + (lane & 7)) * ROWB
                                   + ks * 32 + ((lane >> 3) & 1) * 16;
                ldsm_x4(kb,  st + off);
                ldsm_x4(klb, st + KVTILE + off);
                mma_f16(s[2 * gp],     qh[ks], kb);
                mma_f16(s[2 * gp],     qh[ks], klb);
                mma_f16(s[2 * gp + 1], qh[ks], kb + 2);
                mma_f16(s[2 * gp + 1], qh[ks], klb + 2);
            }
        }

        // ---- softmax (log2 domain) ----
        const float* fac = s_fac[sb];
        float tm0 = -1e30f, tm1 = -1e30f;
#pragma unroll
        for (int nt = 0; nt < 8; ++nt) {
            const int c0 = nt * 8 + (lane & 3) * 2;
            const float f0 = fac[c0], f1 = fac[c0 + 1];
            s[nt][0] *= f0; s[nt][1] *= f1;
            s[nt][2] *= f0; s[nt][3] *= f1;
            tm0 = fmaxf(tm0, fmaxf(s[nt][0], s[nt][1]));
            tm1 = fmaxf(tm1, fmaxf(s[nt][2], s[nt][3]));
        }
        tm0 = fmaxf(tm0, __shfl_xor_sync(0xffffffffu, tm0, 1));
        tm0 = fmaxf(tm0, __shfl_xor_sync(0xffffffffu, tm0, 2));
        tm1 = fmaxf(tm1, __shfl_xor_sync(0xffffffffu, tm1, 1));
        tm1 = fmaxf(tm1, __shfl_xor_sync(0xffffffffu, tm1, 2));
        const float mn0 = fmaxf(m0, tm0), mn1 = fmaxf(m1, tm1);
        const float a0 = fexp2(m0 - mn0), a1 = fexp2(m1 - mn1);
        m0 = mn0; m1 = mn1;
        l0 *= a0; l1 *= a1;
#pragma unroll
        for (int nt = 0; nt < 8; ++nt) {
            o[nt][0] *= a0; o[nt][1] *= a0;
            o[nt][2] *= a1; o[nt][3] *= a1;
        }

        uint32_t pA[4][4];
        float sl0 = 0.f, sl1 = 0.f;
#pragma unroll
        for (int nt = 0; nt < 8; ++nt) {
            const float p0 = fexp2(s[nt][0] - m0), p1 = fexp2(s[nt][1] - m0);
            const float p2 = fexp2(s[nt][2] - m1), p3 = fexp2(s[nt][3] - m1);
            sl0 += p0 + p1; sl1 += p2 + p3;
            pA[nt >> 1][(nt & 1) * 2 + 0] = pack_f16(p0, p1);
            pA[nt >> 1][(nt & 1) * 2 + 1] = pack_f16(p2, p3);
        }
        sl0 += __shfl_xor_sync(0xffffffffu, sl0, 1);
        sl0 += __shfl_xor_sync(0xffffffffu, sl0, 2);
        sl1 += __shfl_xor_sync(0xffffffffu, sl1, 1);
        sl1 += __shfl_xor_sync(0xffffffffu, sl1, 2);
        l0 += sl0; l1 += sl1;

        // ---- PV: o += P · V (single fp16 V) ----
#pragma unroll
        for (int ks = 0; ks < 4; ++ks) {
#pragma unroll
            for (int np = 0; np < 4; ++np) {
                uint32_t vb[4];
                const uint32_t off = (ks * 16 + ((lane >> 3) & 1) * 8 + (lane & 7)) * ROWB
                                   + np * 32 + (lane >> 4) * 16;
                ldsm_x4_t(vb, st + 2 * KVTILE + off);
                mma_f16(o[2 * np],     pA[ks], vb);
                mma_f16(o[2 * np + 1], pA[ks], vb + 2);
            }
        }
        __syncthreads();
    }

    // ---- epilogue: o/l -> ctx single fp16 [t][h*64+dk] ----
    const float inv0 = 1.f / l0, inv1 = 1.f / l1;
    const int trow0 = bfi * SLEN + q0 + wid * 16 + (lane >> 2);
    const int colb = (bh & 7) * 64 + (lane & 3) * 2;
#pragma unroll
    for (int nt = 0; nt < 8; ++nt) {
        const int col = colb + nt * 8;
        const size_t i0 = ((size_t)trow0 * DMOD + col) >> 1;
        const size_t i1 = i0 + (8 * DMOD / 2);
        f162 a;
        a.x = __float2half_rn(o[nt][0] * inv0);
        a.y = __float2half_rn(o[nt][1] * inv0);
        ((f162*)g_c1)[i0] = a;
        a.x = __float2half_rn(o[nt][2] * inv1);
        a.y = __float2half_rn(o[nt][3] * inv1);
        ((f162*)g_c1)[i1] = a;
    }
}

// ===========================================================================
// Residual + LayerNorm; SPLIT=1 also emits single fp16 of the output.
// ===========================================================================
template<int SPLIT>
__global__ __launch_bounds__(256) void ln_kernel(
    const float* __restrict__ X, const float* __restrict__ Y,
    const float* __restrict__ gam, const float* __restrict__ bet,
    float* __restrict__ out, f162* __restrict__ oh)
{
    const int lane = threadIdx.x & 31;
    const int t = (blockIdx.x << 3) + (threadIdx.x >> 5);
    const float4* xp = (const float4*)(X + (size_t)t * DMOD);
    const float4* yp = (const float4*)(Y + (size_t)t * DMOD);

    float4 r[4];
    float sum = 0.f, sq = 0.f;
#pragma unroll
    for (int i = 0; i < 4; ++i) {
        const int idx = lane + (i << 5);
        float4 a = xp[idx], b = yp[idx];
        float4 v = make_float4(a.x + b.x, a.y + b.y, a.z + b.z, a.w + b.w);
        r[i] = v;
        sum += (v.x + v.y) + (v.z + v.w);
        sq  += (v.x * v.x + v.y * v.y) + (v.z * v.z + v.w * v.w);
    }
#pragma unroll
    for (int off = 16; off; off >>= 1) {
        sum += __shfl_xor_sync(0xffffffffu, sum, off);
        sq  += __shfl_xor_sync(0xffffffffu, sq, off);
    }
    const float mean = sum * (1.0f / 512.0f);
    const float var  = sq * (1.0f / 512.0f) - mean * mean;
    const float rstd = rsqrtf(var + 1e-5f);

    float4* op = (float4*)(out + (size_t)t * DMOD);
    const float4* gp = (const float4*)gam;
    const float4* bp = (const float4*)bet;
#pragma unroll
    for (int i = 0; i < 4; ++i) {
        const int idx = lane + (i << 5);
        float4 g = gp[idx], be = bp[idx], v = r[i];
        float4 o4;
        o4.x = (v.x - mean) * rstd * g.x + be.x;
        o4.y = (v.y - mean) * rstd * g.y + be.y;
        o4.z = (v.z - mean) * rstd * g.z + be.z;
        o4.w = (v.w - mean) * rstd * g.w + be.w;
        op[idx] = o4;
        if (SPLIT) {
            f162 a, b2;
            a.x = __float2half_rn(o4.x); a.y = __float2half_rn(o4.y);
            b2.x = __float2half_rn(o4.z); b2.y = __float2half_rn(o4.w);
            oh[(size_t)t * 256 + idx * 2]     = a;
            oh[(size_t)t * 256 + idx * 2 + 1] = b2;
        }
    }
}

// ===========================================================================
extern "C" void kernel_launch(void* const* d_in, const int* in_sizes, int n_in,
                              void* d_out, int out_size)
{
    const float* x   = (const float*)d_in[0];
    const unsigned int* mask = (const unsigned int*)d_in[1];
    const float* wq  = (const float*)d_in[2];
    const float* bq  = (const float*)d_in[3];
    const float* wk  = (const float*)d_in[4];
    const float* bk  = (const float*)d_in[5];
    const float* wv  = (const float*)d_in[6];
    const float* bv  = (const float*)d_in[7];
    const float* wo  = (const float*)d_in[8];
    const float* bo  = (const float*)d_in[9];
    const float* w1  = (const float*)d_in[10];
    const float* b1  = (const float*)d_in[11];
    const float* w2  = (const float*)d_in[12];
    const float* b2  = (const float*)d_in[13];
    const float* g1  = (const float*)d_in[14];
    const float* be1 = (const float*)d_in[15];
    const float* g2  = (const float*)d_in[16];
    const float* be2 = (const float*)d_in[17];
    float* out = (float*)d_out;

    float *t1_p, *h_p;
    f16 *x1, *c1, *h1, *f1, *wh, *wl;
    cudaGetSymbolAddress((void**)&t1_p, g_t1);
    cudaGetSymbolAddress((void**)&h_p, g_h);
    cudaGetSymbolAddress((void**)&x1, g_x1);
    cudaGetSymbolAddress((void**)&c1, g_c1);
    cudaGetSymbolAddress((void**)&h1, g_h1);
    cudaGetSymbolAddress((void**)&f1, g_f1);
    cudaGetSymbolAddress((void**)&wh, g_wh);
    cudaGetSymbolAddress((void**)&wl, g_wl);

    cudaFuncSetAttribute(tc_gemm<0>, cudaFuncAttributeMaxDynamicSharedMemorySize, GEMM_SMEM);
    cudaFuncSetAttribute(tc_gemm<1>, cudaFuncAttributeMaxDynamicSharedMemorySize, GEMM_SMEM);
    cudaFuncSetAttribute(tc_gemm<2>, cudaFuncAttributeMaxDynamicSharedMemorySize, GEMM_SMEM);
    cudaFuncSetAttribute(attn_mma,   cudaFuncAttributeMaxDynamicSharedMemorySize, ATTN_SMEM);

    // 0) all splits (weights hi/lo + x single) in ONE launch
    split_all<<<19456, 256>>>((const float4*)wq, (const float4*)wk,
        (const float4*)wv, (const float4*)wo, (const float4*)w1, (const float4*)w2,
        (const float4*)x, (f162*)wh, (f162*)wl, (f162*)x1);

    // 1) QKV (z = 0/1/2) -> q single / k hi-lo / v single in [bh][s][dk]
    tc_gemm<2><<<dim3(4, 256, 3), 256, GEMM_SMEM>>>(x1, 512, 512,
        wh, wl, bq, bk, bv, nullptr, nullptr);

    // 2) tensor-core attention -> ctx single fp16
    attn_mma<<<dim3(8, 256), 256, ATTN_SMEM>>>(mask);

    // 3) O-proj -> t1 (fp32)
    tc_gemm<0><<<dim3(4, 256, 1), 256, GEMM_SMEM>>>(c1, 512, 512,
        wh + 786432, wl + 786432, bo, nullptr, nullptr, t1_p, nullptr);

    // 4) h = LN(x + attn_out); also single fp16 of h
    ln_kernel<1><<<NTOK / 8, 256>>>(x, t1_p, g1, be1, h_p, (f162*)h1);

    // 5) FFN up + GELU -> ff single fp16
    tc_gemm<1><<<dim3(16, 256, 1), 256, GEMM_SMEM>>>(h1, 512, 2048,
        wh + 1048576, wl + 1048576, b1, nullptr, nullptr, nullptr, f1);

    // 6) FFN down -> t1 (fp32)
    tc_gemm<0><<<dim3(4, 256, 1), 256, GEMM_SMEM>>>(f1, 2048, 512,
        wh + 2097152, wl + 2097152, b2, nullptr, nullptr, t1_p, nullptr);

    // 7) out = LN(h + ffn_out)
    ln_kernel<0><<<NTOK / 8, 256>>>(h_p, t1_p, g2, be2, out, nullptr);
}

// round 16
// speedup vs baseline: 1.5839x; 1.4429x over previous
#include <cuda_runtime.h>
#include <cuda_fp16.h>
#include <math.h>
#include <stdint.h>

#define NTOK 32768
#define SLEN 1024
#define DMOD 512
#define DFF  2048
#define NBH  256
#define HDK  64
#define BHSZ 16777216   // NBH*SLEN*HDK

typedef __half  f16;
typedef __half2 f162;

// ---- device scratch (no allocation allowed) ----
__device__ __align__(16) float g_t1[NTOK * DMOD];
__device__ __align__(16) float g_h[NTOK * DMOD];
__device__ __align__(16) f16  g_x1[NTOK * DMOD];          // x fp16
__device__ __align__(16) f16  g_c1[NTOK * DMOD];          // ctx fp16
__device__ __align__(16) f16  g_h1[NTOK * DMOD];          // h fp16
__device__ __align__(16) f16  g_f1[NTOK * DFF];           // ff fp16
__device__ __align__(16) f16  g_w1[3145728];              // all weights fp16
__device__ __align__(16) f16  g_q1[BHSZ];                 // q
__device__ __align__(16) f16  g_kv2[2][BHSZ];             // k, v
// weight offsets in g_w1 (elems): q=0 k=262144 v=524288 o=786432 w1=1048576 w2=2097152

// ---- helpers ----
__device__ __forceinline__ uint32_t smem_u32(const void* p) {
    uint32_t a;
    asm("{ .reg .u64 t; cvta.to.shared.u64 t, %1; cvt.u32.u64 %0, t; }" : "=r"(a) : "l"(p));
    return a;
}
__device__ __forceinline__ void ldsm_x4(uint32_t* r, uint32_t a) {
    asm volatile("ldmatrix.sync.aligned.m8n8.x4.shared.b16 {%0,%1,%2,%3}, [%4];"
        : "=r"(r[0]), "=r"(r[1]), "=r"(r[2]), "=r"(r[3]) : "r"(a));
}
__device__ __forceinline__ void ldsm_x4_t(uint32_t* r, uint32_t a) {
    asm volatile("ldmatrix.sync.aligned.m8n8.x4.trans.shared.b16 {%0,%1,%2,%3}, [%4];"
        : "=r"(r[0]), "=r"(r[1]), "=r"(r[2]), "=r"(r[3]) : "r"(a));
}
__device__ __forceinline__ void ldsm_x2(uint32_t* r, uint32_t a) {
    asm volatile("ldmatrix.sync.aligned.m8n8.x2.shared.b16 {%0,%1}, [%2];"
        : "=r"(r[0]), "=r"(r[1]) : "r"(a));
}
__device__ __forceinline__ void mma_f16(float* c, const uint32_t* a, const uint32_t* b) {
    asm volatile("mma.sync.aligned.m16n8k16.row.col.f32.f16.f16.f32 "
        "{%0,%1,%2,%3}, {%4,%5,%6,%7}, {%8,%9}, {%0,%1,%2,%3};"
        : "+f"(c[0]), "+f"(c[1]), "+f"(c[2]), "+f"(c[3])
        : "r"(a[0]), "r"(a[1]), "r"(a[2]), "r"(a[3]), "r"(b[0]), "r"(b[1]));
}
__device__ __forceinline__ uint32_t pack_f16(float lo, float hi) {
    uint32_t r;
    asm("cvt.rn.f16x2.f32 %0, %1, %2;" : "=r"(r) : "f"(hi), "f"(lo));
    return r;
}
// fast exp2 on FMA pipe: floor + deg-5 poly + exponent splice (x <= 0)
__device__ __forceinline__ float fexp2(float x) {
    x = fmaxf(x, -110.0f);
    float fl = floorf(x);
    float f = x - fl;
    float p = 0.0013334f;
    p = p * f + 0.0096183f;
    p = p * f + 0.0555042f;
    p = p * f + 0.2402265f;
    p = p * f + 0.6931472f;
    p = p * f + 1.0f;
    return p * __int_as_float(((int)fl + 127) << 23);
}
#define CP_ASYNC16(dst, src) \
    asm volatile("cp.async.cg.shared.global [%0], [%1], 16;" :: "r"(dst), "l"(src))
#define CP_COMMIT() asm volatile("cp.async.commit_group;" ::: "memory")
#define CP_WAIT1()  asm volatile("cp.async.wait_group 1;" ::: "memory")
#define CP_WAIT0()  asm volatile("cp.async.wait_group 0;" ::: "memory")

// ===========================================================================
// Unified fp32 -> fp16 conversion for all 7 tensors (one launch).
// Blocks [0,1024): wq/wk/wv/wo  [1024,2048): w1  [2048,3072): w2  rest: x
// ===========================================================================
__global__ __launch_bounds__(256) void split_all(
    const float4* __restrict__ wq, const float4* __restrict__ wk,
    const float4* __restrict__ wv, const float4* __restrict__ wo,
    const float4* __restrict__ w1, const float4* __restrict__ w2,
    const float4* __restrict__ x,
    f162* __restrict__ wd, f162* __restrict__ xd)
{
    const int b = blockIdx.x;
    const float4* src; f162* dst; int i;
    if (b < 1024) {
        const int seg = b >> 8;
        src = (seg == 0) ? wq : (seg == 1) ? wk : (seg == 2) ? wv : wo;
        i = (b & 255) * 256 + threadIdx.x;
        dst = wd + (size_t)seg * 131072;
    } else if (b < 2048) {
        src = w1; i = (b - 1024) * 256 + threadIdx.x; dst = wd + 524288;
    } else if (b < 3072) {
        src = w2; i = (b - 2048) * 256 + threadIdx.x; dst = wd + 1048576;
    } else {
        src = x;  i = (b - 3072) * 256 + threadIdx.x; dst = xd;
    }
    float4 v = src[i];
    f162 a, bb;
    a.x = __float2half_rn(v.x); a.y = __float2half_rn(v.y);
    bb.x = __float2half_rn(v.z); bb.y = __float2half_rn(v.w);
    dst[2 * i] = a; dst[2 * i + 1] = bb;
}

// ===========================================================================
// fp16 single-MMA GEMM (NT): C[m,n] = sum_k A[m,k]*W[n,k] + bias[n]
// 128x128 CTA tile, 8 warps of 64x32, BK=32, 3-stage cp.async WAIT1,
// 2 tiles/stage = 28.7KB -> 86KB total -> 2 CTAs/SM.
// MODE 0: fp32 store  MODE 1: GELU -> fp16  MODE 2: QKV scatter (z: q/k/v)
// ===========================================================================
#define PADC 56
#define TILE_BYTES (128 * PADC * 2)     // 14336
#define STG_BYTES  (2 * TILE_BYTES)     // 28672
#define GEMM_SMEM  (3 * STG_BYTES)      // 86016

template<int MODE>
__global__ __launch_bounds__(256, 2) void tc_gemm(
    const f16* __restrict__ A, int K, int N,
    const f16* __restrict__ W,
    const float* __restrict__ b0, const float* __restrict__ b1, const float* __restrict__ b2,
    float* __restrict__ C0, f16* __restrict__ F0)
{
    const float* bias = b0; float* C = C0;
    f16* Hd = F0;
    if (MODE == 2) {
        W += (size_t)blockIdx.z * 262144;
        if (blockIdx.z == 0)      { Hd = g_q1; }
        else if (blockIdx.z == 1) { Hd = g_kv2[0]; bias = b1; }
        else                      { Hd = g_kv2[1]; bias = b2; }
    }
    extern __shared__ char dynsm[];
    const uint32_t smb = smem_u32(dynsm);

    const int tid = threadIdx.x;
    const int lane = tid & 31;
    const int wr = (tid >> 5) >> 2;      // 0..1
    const int wc = (tid >> 5) & 3;       // 0..3
    const int bm = blockIdx.y << 7, bn = blockIdx.x << 7;
    const int nch = K >> 5;

    const int row = tid >> 1, half = tid & 1;
    const f16* pa = A + (size_t)(bm + row) * K + half * 16;
    const f16* pb = W + (size_t)(bn + row) * K + half * 16;
    const uint32_t sdst = smb + row * 112 + half * 32;

#define LOAD_CHUNK(c, s) do { \
    const uint32_t d_ = sdst + (uint32_t)(s) * STG_BYTES; \
    const size_t  g_ = (size_t)(c) * 32; \
    CP_ASYNC16(d_,                   pa + g_); \
    CP_ASYNC16(d_ + 16,              pa + g_ + 8); \
    CP_ASYNC16(d_ + TILE_BYTES,      pb + g_); \
    CP_ASYNC16(d_ + TILE_BYTES + 16, pb + g_ + 8); \
} while (0)

    uint32_t arow_off[4], brow_off[4];
#pragma unroll
    for (int mi = 0; mi < 4; ++mi)
        arow_off[mi] = (uint32_t)((wr * 64 + mi * 16 + (lane & 15)) * 112 + (lane >> 4) * 16);
#pragma unroll
    for (int ni = 0; ni < 4; ++ni)
        brow_off[ni] = (uint32_t)((wc * 32 + ni * 8 + (lane & 7)) * 112 + ((lane >> 3) & 1) * 16);

    float acc[4][4][4];
#pragma unroll
    for (int mi = 0; mi < 4; ++mi)
#pragma unroll
        for (int ni = 0; ni < 4; ++ni)
#pragma unroll
            for (int t = 0; t < 4; ++t) acc[mi][ni][t] = 0.f;

    LOAD_CHUNK(0, 0); CP_COMMIT();
    LOAD_CHUNK(1, 1); CP_COMMIT();

    for (int c = 0; c < nch; ++c) {
        CP_WAIT1();
        __syncthreads();
        if (c + 2 < nch) LOAD_CHUNK(c + 2, (c + 2) % 3);
        CP_COMMIT();

        const uint32_t sA = smb + (uint32_t)(c % 3) * STG_BYTES;
#pragma unroll
        for (int ks = 0; ks < 2; ++ks) {
            uint32_t ah[4][4], bh[4][2];
#pragma unroll
            for (int mi = 0; mi < 4; ++mi)
                ldsm_x4(ah[mi], sA + arow_off[mi] + ks * 32);
#pragma unroll
            for (int ni = 0; ni < 4; ++ni)
                ldsm_x2(bh[ni], sA + TILE_BYTES + brow_off[ni] + ks * 32);
#pragma unroll
            for (int mi = 0; mi < 4; ++mi)
#pragma unroll
                for (int ni = 0; ni < 4; ++ni)
                    mma_f16(acc[mi][ni], ah[mi], bh[ni]);
        }
    }

    // ---- epilogue ----
#pragma unroll
    for (int mi = 0; mi < 4; ++mi) {
#pragma unroll
        for (int ni = 0; ni < 4; ++ni) {
            const int col = bn + wc * 32 + ni * 8 + (lane & 3) * 2;
            const float2 bb = *(const float2*)(bias + col);
#pragma unroll
            for (int hrow = 0; hrow < 2; ++hrow) {
                const int r = bm + wr * 64 + mi * 16 + (lane >> 2) + hrow * 8;
                float v0 = acc[mi][ni][hrow * 2 + 0] + bb.x;
                float v1 = acc[mi][ni][hrow * 2 + 1] + bb.y;
                if (MODE == 1) {
                    v0 = 0.5f * v0 * (1.0f + erff(v0 * 0.70710678118654752f));
                    v1 = 0.5f * v1 * (1.0f + erff(v1 * 0.70710678118654752f));
                    f162 a;
                    a.x = __float2half_rn(v0); a.y = __float2half_rn(v1);
                    ((f162*)Hd)[((size_t)r * N + col) >> 1] = a;
                } else if (MODE == 2) {
                    const int hidx = ((r >> 10) << 3) + (col >> 6);
                    const size_t idx = (size_t)hidx * (SLEN * HDK)
                                     + ((r & 1023) << 6) + (col & 63);
                    f162 a;
                    a.x = __float2half_rn(v0); a.y = __float2half_rn(v1);
                    ((f162*)Hd)[idx >> 1] = a;
                } else {
                    *(float2*)(C + (size_t)r * N + col) = make_float2(v0, v1);
                }
            }
        }
    }
}

// ===========================================================================
// Tensor-core flash attention, fp16. 2 CTAs/SM.
// grid=(8, 256), block=256 (8 warps, 16 query rows each).
// QK = 1 MMA, PV = 1 MMA. 2-stage double-buffered K/V (18.4KB/stage).
// ===========================================================================
#define ROWB 144
#define KVTILE (64 * ROWB)        // 9216
#define STAGEB (2 * KVTILE)       // 18432
#define ATTN_SMEM (2 * STAGEB)    // 36864

__global__ __launch_bounds__(256, 2) void attn_mma(const unsigned int* __restrict__ mask)
{
    extern __shared__ char sm[];
    __shared__ float s_fac[2][64];
    const uint32_t smb = smem_u32(sm);
    const int tid = threadIdx.x, wid = tid >> 5, lane = tid & 31;
    const int bh = blockIdx.y;
    const int bfi = bh >> 3, bb = bfi >> 3;
    const int q0 = blockIdx.x << 7;
    const float FB = 0.25f  * 1.4426950408889634f;
    const float FN = 0.125f * 1.4426950408889634f;

    // ---- stage Q through smem into A-fragments ----
#pragma unroll
    for (int i = 0; i < 4; ++i) {
        const int cid = tid + (i << 8);                  // 0..1023
        const int row = cid >> 3, c = cid & 7;
        const f16* src = g_q1 + ((size_t)bh << 16) + (size_t)(q0 + row) * 64 + c * 8;
        CP_ASYNC16(smb + row * ROWB + c * 16, src);
    }
    CP_COMMIT();
    CP_WAIT0();
    __syncthreads();

    uint32_t qh[4][4];
#pragma unroll
    for (int ks = 0; ks < 4; ++ks) {
        const uint32_t off = (wid * 16 + (lane & 15)) * ROWB + ks * 32 + (lane >> 4) * 16;
        ldsm_x4(qh[ks], smb + off);
    }
    __syncthreads();

    float o[8][4];
#pragma unroll
    for (int nt = 0; nt < 8; ++nt)
#pragma unroll
        for (int t = 0; t < 4; ++t) o[nt][t] = 0.f;
    float m0 = -1e30f, m1 = -1e30f, l0 = 0.f, l1 = 0.f;

#define LOAD_KV(kt_, st_) do { \
    _Pragma("unroll") \
    for (int i = 0; i < 4; ++i) { \
        const int cid = tid + (i << 8); \
        const int arr = cid >> 9, rem = cid & 511; \
        const int row = rem >> 3, cc = rem & 7; \
        const f16* src = g_kv2[arr] + ((size_t)bh << 16) \
                       + (size_t)(((kt_) << 6) + row) * 64 + cc * 8; \
        CP_ASYNC16(smb + (st_) * STAGEB + arr * KVTILE + row * ROWB + cc * 16, src); \
    } \
} while (0)

    LOAD_KV(0, 0);
    CP_COMMIT();
    if (tid < 64) s_fac[0][tid] = mask[bb * SLEN + tid] ? FB : FN;

    for (int kt = 0; kt < 16; ++kt) {
        const int sb = kt & 1;
        if (kt < 15) {
            LOAD_KV(kt + 1, sb ^ 1);
            CP_COMMIT();
            if (tid < 64)
                s_fac[sb ^ 1][tid] = mask[bb * SLEN + (kt + 1) * 64 + tid] ? FB : FN;
            CP_WAIT1();
        } else {
            CP_WAIT0();
        }
        __syncthreads();
        const uint32_t st = smb + sb * STAGEB;

        // ---- QK (single MMA per tile) ----
        float s[8][4];
#pragma unroll
        for (int nt = 0; nt < 8; ++nt)
#pragma unroll
            for (int t = 0; t < 4; ++t) s[nt][t] = 0.f;
#pragma unroll
        for (int ks = 0; ks < 4; ++ks) {
#pragma unroll
            for (int gp = 0; gp < 4; ++gp) {
                uint32_t kb[4];
                const uint32_t off = (gp * 16 + ((lane >> 4) << 3) + (lane & 7)) * ROWB
                                   + ks * 32 + ((lane >> 3) & 1) * 16;
                ldsm_x4(kb, st + off);
                mma_f16(s[2 * gp],     qh[ks], kb);
                mma_f16(s[2 * gp + 1], qh[ks], kb + 2);
            }
        }

        // ---- softmax (log2 domain) ----
        const float* fac = s_fac[sb];
        float tm0 = -1e30f, tm1 = -1e30f;
#pragma unroll
        for (int nt = 0; nt < 8; ++nt) {
            const int c0 = nt * 8 + (lane & 3) * 2;
            const float f0 = fac[c0], f1 = fac[c0 + 1];
            s[nt][0] *= f0; s[nt][1] *= f1;
            s[nt][2] *= f0; s[nt][3] *= f1;
            tm0 = fmaxf(tm0, fmaxf(s[nt][0], s[nt][1]));
            tm1 = fmaxf(tm1, fmaxf(s[nt][2], s[nt][3]));
        }
        tm0 = fmaxf(tm0, __shfl_xor_sync(0xffffffffu, tm0, 1));
        tm0 = fmaxf(tm0, __shfl_xor_sync(0xffffffffu, tm0, 2));
        tm1 = fmaxf(tm1, __shfl_xor_sync(0xffffffffu, tm1, 1));
        tm1 = fmaxf(tm1, __shfl_xor_sync(0xffffffffu, tm1, 2));
        const float mn0 = fmaxf(m0, tm0), mn1 = fmaxf(m1, tm1);
        const float a0 = fexp2(m0 - mn0), a1 = fexp2(m1 - mn1);
        m0 = mn0; m1 = mn1;
        l0 *= a0; l1 *= a1;
#pragma unroll
        for (int nt = 0; nt < 8; ++nt) {
            o[nt][0] *= a0; o[nt][1] *= a0;
            o[nt][2] *= a1; o[nt][3] *= a1;
        }

        uint32_t pA[4][4];
        float sl0 = 0.f, sl1 = 0.f;
#pragma unroll
        for (int nt = 0; nt < 8; ++nt) {
            const float p0 = fexp2(s[nt][0] - m0), p1 = fexp2(s[nt][1] - m0);
            const float p2 = fexp2(s[nt][2] - m1), p3 = fexp2(s[nt][3] - m1);
            sl0 += p0 + p1; sl1 += p2 + p3;
            pA[nt >> 1][(nt & 1) * 2 + 0] = pack_f16(p0, p1);
            pA[nt >> 1][(nt & 1) * 2 + 1] = pack_f16(p2, p3);
        }
        sl0 += __shfl_xor_sync(0xffffffffu, sl0, 1);
        sl0 += __shfl_xor_sync(0xffffffffu, sl0, 2);
        sl1 += __shfl_xor_sync(0xffffffffu, sl1, 1);
        sl1 += __shfl_xor_sync(0xffffffffu, sl1, 2);
        l0 += sl0; l1 += sl1;

        // ---- PV ----
#pragma unroll
        for (int ks = 0; ks < 4; ++ks) {
#pragma unroll
            for (int np = 0; np < 4; ++np) {
                uint32_t vb[4];
                const uint32_t off = (ks * 16 + ((lane >> 3) & 1) * 8 + (lane & 7)) * ROWB
                                   + np * 32 + (lane >> 4) * 16;
                ldsm_x4_t(vb, st + KVTILE + off);
                mma_f16(o[2 * np],     pA[ks], vb);
                mma_f16(o[2 * np + 1], pA[ks], vb + 2);
            }
        }
        __syncthreads();
    }

    // ---- epilogue: o/l -> ctx fp16 [t][h*64+dk] ----
    const float inv0 = 1.f / l0, inv1 = 1.f / l1;
    const int trow0 = bfi * SLEN + q0 + wid * 16 + (lane >> 2);
    const int colb = (bh & 7) * 64 + (lane & 3) * 2;
#pragma unroll
    for (int nt = 0; nt < 8; ++nt) {
        const int col = colb + nt * 8;
        const size_t i0 = ((size_t)trow0 * DMOD + col) >> 1;
        const size_t i1 = i0 + (8 * DMOD / 2);
        f162 a;
        a.x = __float2half_rn(o[nt][0] * inv0);
        a.y = __float2half_rn(o[nt][1] * inv0);
        ((f162*)g_c1)[i0] = a;
        a.x = __float2half_rn(o[nt][2] * inv1);
        a.y = __float2half_rn(o[nt][3] * inv1);
        ((f162*)g_c1)[i1] = a;
    }
}

// ===========================================================================
// Residual + LayerNorm; SPLIT=1 also emits fp16 of the output.
// ===========================================================================
template<int SPLIT>
__global__ __launch_bounds__(256) void ln_kernel(
    const float* __restrict__ X, const float* __restrict__ Y,
    const float* __restrict__ gam, const float* __restrict__ bet,
    float* __restrict__ out, f162* __restrict__ oh)
{
    const int lane = threadIdx.x & 31;
    const int t = (blockIdx.x << 3) + (threadIdx.x >> 5);
    const float4* xp = (const float4*)(X + (size_t)t * DMOD);
    const float4* yp = (const float4*)(Y + (size_t)t * DMOD);

    float4 r[4];
    float sum = 0.f, sq = 0.f;
#pragma unroll
    for (int i = 0; i < 4; ++i) {
        const int idx = lane + (i << 5);
        float4 a = xp[idx], b = yp[idx];
        float4 v = make_float4(a.x + b.x, a.y + b.y, a.z + b.z, a.w + b.w);
        r[i] = v;
        sum += (v.x + v.y) + (v.z + v.w);
        sq  += (v.x * v.x + v.y * v.y) + (v.z * v.z + v.w * v.w);
    }
#pragma unroll
    for (int off = 16; off; off >>= 1) {
        sum += __shfl_xor_sync(0xffffffffu, sum, off);
        sq  += __shfl_xor_sync(0xffffffffu, sq, off);
    }
    const float mean = sum * (1.0f / 512.0f);
    const float var  = sq * (1.0f / 512.0f) - mean * mean;
    const float rstd = rsqrtf(var + 1e-5f);

    float4* op = (float4*)(out + (size_t)t * DMOD);
    const float4* gp = (const float4*)gam;
    const float4* bp = (const float4*)bet;
#pragma unroll
    for (int i = 0; i < 4; ++i) {
        const int idx = lane + (i << 5);
        float4 g = gp[idx], be = bp[idx], v = r[i];
        float4 o4;
        o4.x = (v.x - mean) * rstd * g.x + be.x;
        o4.y = (v.y - mean) * rstd * g.y + be.y;
        o4.z = (v.z - mean) * rstd * g.z + be.z;
        o4.w = (v.w - mean) * rstd * g.w + be.w;
        op[idx] = o4;
        if (SPLIT) {
            f162 a, b2;
            a.x = __float2half_rn(o4.x); a.y = __float2half_rn(o4.y);
            b2.x = __float2half_rn(o4.z); b2.y = __float2half_rn(o4.w);
            oh[(size_t)t * 256 + idx * 2]     = a;
            oh[(size_t)t * 256 + idx * 2 + 1] = b2;
        }
    }
}

// ===========================================================================
extern "C" void kernel_launch(void* const* d_in, const int* in_sizes, int n_in,
                              void* d_out, int out_size)
{
    const float* x   = (const float*)d_in[0];
    const unsigned int* mask = (const unsigned int*)d_in[1];
    const float* wq  = (const float*)d_in[2];
    const float* bq  = (const float*)d_in[3];
    const float* wk  = (const float*)d_in[4];
    const float* bk  = (const float*)d_in[5];
    const float* wv  = (const float*)d_in[6];
    const float* bv  = (const float*)d_in[7];
    const float* wo  = (const float*)d_in[8];
    const float* bo  = (const float*)d_in[9];
    const float* w1  = (const float*)d_in[10];
    const float* b1  = (const float*)d_in[11];
    const float* w2  = (const float*)d_in[12];
    const float* b2  = (const float*)d_in[13];
    const float* g1  = (const float*)d_in[14];
    const float* be1 = (const float*)d_in[15];
    const float* g2  = (const float*)d_in[16];
    const float* be2 = (const float*)d_in[17];
    float* out = (float*)d_out;

    float *t1_p, *h_p;
    f16 *x1, *c1, *h1, *f1, *w_p;
    cudaGetSymbolAddress((void**)&t1_p, g_t1);
    cudaGetSymbolAddress((void**)&h_p, g_h);
    cudaGetSymbolAddress((void**)&x1, g_x1);
    cudaGetSymbolAddress((void**)&c1, g_c1);
    cudaGetSymbolAddress((void**)&h1, g_h1);
    cudaGetSymbolAddress((void**)&f1, g_f1);
    cudaGetSymbolAddress((void**)&w_p, g_w1);

    cudaFuncSetAttribute(tc_gemm<0>, cudaFuncAttributeMaxDynamicSharedMemorySize, GEMM_SMEM);
    cudaFuncSetAttribute(tc_gemm<1>, cudaFuncAttributeMaxDynamicSharedMemorySize, GEMM_SMEM);
    cudaFuncSetAttribute(tc_gemm<2>, cudaFuncAttributeMaxDynamicSharedMemorySize, GEMM_SMEM);
    cudaFuncSetAttribute(attn_mma,   cudaFuncAttributeMaxDynamicSharedMemorySize, ATTN_SMEM);

    // 0) all conversions (weights + x -> fp16) in ONE launch
    split_all<<<19456, 256>>>((const float4*)wq, (const float4*)wk,
        (const float4*)wv, (const float4*)wo, (const float4*)w1, (const float4*)w2,
        (const float4*)x, (f162*)w_p, (f162*)x1);

    // 1) QKV (z = 0/1/2) -> q / k / v fp16 in [bh][s][dk]
    tc_gemm<2><<<dim3(4, 256, 3), 256, GEMM_SMEM>>>(x1, 512, 512,
        w_p, bq, bk, bv, nullptr, nullptr);

    // 2) tensor-core attention -> ctx fp16
    attn_mma<<<dim3(8, 256), 256, ATTN_SMEM>>>(mask);

    // 3) O-proj -> t1 (fp32)
    tc_gemm<0><<<dim3(4, 256, 1), 256, GEMM_SMEM>>>(c1, 512, 512,
        w_p + 786432, bo, nullptr, nullptr, t1_p, nullptr);

    // 4) h = LN(x + attn_out); also fp16 of h
    ln_kernel<1><<<NTOK / 8, 256>>>(x, t1_p, g1, be1, h_p, (f162*)h1);

    // 5) FFN up + GELU -> ff fp16
    tc_gemm<1><<<dim3(16, 256, 1), 256, GEMM_SMEM>>>(h1, 512, 2048,
        w_p + 1048576, b1, nullptr, nullptr, nullptr, f1);

    // 6) FFN down -> t1 (fp32)
    tc_gemm<0><<<dim3(4, 256, 1), 256, GEMM_SMEM>>>(f1, 2048, 512,
        w_p + 2097152, b2, nullptr, nullptr, t1_p, nullptr);

    // 7) out = LN(h + ffn_out)
    ln_kernel<0><<<NTOK / 8, 256>>>(h_p, t1_p, g2, be2, out, nullptr);
}